// round 1
// baseline (speedup 1.0000x reference)
#include <cuda_runtime.h>
#include <cuda_bf16.h>
#include <math.h>

// Problem constants
#define B_    2
#define HH    256
#define WWF   256
#define C_    180
#define C4    720
#define H2    128
#define W2    128
#define NH_   6
#define D_    30
#define DV    120
#define NQ    64
#define NK    144
#define NWIN  512
#define NPOS2 (B_*H2*W2)     // 32768
#define NTOK  (B_*HH*WWF)    // 131072

#define ATTN_SMEM ((NQ*D_ + NK*D_ + NK*DV + 8*NK) * 4)  // 98688 B

// -------- scratch (device globals; no allocation) --------
__device__ __align__(256) float g_xd[(size_t)NPOS2*C4];
__device__ __align__(256) float g_q [(size_t)NPOS2*C_];
__device__ __align__(256) float g_k [(size_t)NPOS2*C_];
__device__ __align__(256) float g_v [(size_t)NPOS2*C4];
__device__ __align__(256) float g_o [(size_t)NPOS2*C4];
__device__ __align__(256) float g_xr[(size_t)NTOK*C_];
__device__ __align__(256) float g_x1[(size_t)NTOK*C_];
__device__ __align__(256) float g_ln[(size_t)NTOK*C_];
__device__ __align__(256) float g_h [(size_t)NTOK*2*C_];

__device__ __forceinline__ float gelu_f(float x) {
    return 0.5f * x * (1.0f + erff(x * 0.70710678118654752440f));
}

// -------- LayerNorm + DWT fused: one block per (b,y2,x2) --------
__global__ void ln_dwt_kernel(const float* __restrict__ x,
                              const float* __restrict__ w,
                              const float* __restrict__ bias) {
    __shared__ float red[6][8];
    int pos = blockIdx.x;                 // 0..NPOS2-1
    int x2 = pos & 127; int t = pos >> 7;
    int y2 = t & 127;   int b = t >> 7;
    int tid = threadIdx.x;                // 192 threads
    const float* p00 = x + (((size_t)(b*HH + 2*y2))*WWF + 2*x2)*C_;
    float a=0.f, bv=0.f, cv=0.f, dv=0.f;
    if (tid < C_) {
        a  = p00[tid];
        bv = p00[C_ + tid];
        cv = p00[(size_t)WWF*C_ + tid];
        dv = p00[(size_t)WWF*C_ + C_ + tid];
    }
    float q0=a, q1=bv, q2=cv, q3=dv, q4=a*a, q5=bv*bv, q6=cv*cv, q7=dv*dv;
    #pragma unroll
    for (int off = 16; off; off >>= 1) {
        q0 += __shfl_xor_sync(0xffffffffu, q0, off);
        q1 += __shfl_xor_sync(0xffffffffu, q1, off);
        q2 += __shfl_xor_sync(0xffffffffu, q2, off);
        q3 += __shfl_xor_sync(0xffffffffu, q3, off);
        q4 += __shfl_xor_sync(0xffffffffu, q4, off);
        q5 += __shfl_xor_sync(0xffffffffu, q5, off);
        q6 += __shfl_xor_sync(0xffffffffu, q6, off);
        q7 += __shfl_xor_sync(0xffffffffu, q7, off);
    }
    int lane = tid & 31, warp = tid >> 5;
    if (lane == 0) {
        red[warp][0]=q0; red[warp][1]=q1; red[warp][2]=q2; red[warp][3]=q3;
        red[warp][4]=q4; red[warp][5]=q5; red[warp][6]=q6; red[warp][7]=q7;
    }
    __syncthreads();
    float s[8];
    #pragma unroll
    for (int i = 0; i < 8; i++) {
        float acc = 0.f;
        #pragma unroll
        for (int wv = 0; wv < 6; wv++) acc += red[wv][i];
        s[i] = acc;
    }
    if (tid < C_) {
        const float inv = 1.0f / (float)C_;
        float mu0=s[0]*inv, mu1=s[1]*inv, mu2=s[2]*inv, mu3=s[3]*inv;
        float r0 = rsqrtf(s[4]*inv - mu0*mu0 + 1e-5f);
        float r1 = rsqrtf(s[5]*inv - mu1*mu1 + 1e-5f);
        float r2 = rsqrtf(s[6]*inv - mu2*mu2 + 1e-5f);
        float r3 = rsqrtf(s[7]*inv - mu3*mu3 + 1e-5f);
        float ww = w[tid], wb = bias[tid];
        float an = (a  - mu0)*r0*ww + wb;
        float bn = (bv - mu1)*r1*ww + wb;
        float cn = (cv - mu2)*r2*ww + wb;
        float dn = (dv - mu3)*r3*ww + wb;
        float* outp = g_xd + (size_t)pos*C4;
        outp[tid]        = ( an + bn + cn + dn)*0.5f;  // ll
        outp[C_   + tid] = (-an - bn + cn + dn)*0.5f;  // lh
        outp[2*C_ + tid] = (-an + bn - cn + dn)*0.5f;  // hl
        outp[3*C_ + tid] = ( an - bn - cn + dn)*0.5f;  // hh
    }
}

// -------- generic register-tiled SGEMM: C = A(MxK) @ W(KxN) + bias [+epi] --------
// EPI: 0 = bias only, 1 = gelu(bias+acc), 2 = bias+acc+Res
template<int EPI>
__global__ void sgemm_kernel(const float* __restrict__ A, const float* __restrict__ W,
                             const float* __restrict__ bias, const float* __restrict__ Res,
                             float* __restrict__ C, int M, int N, int K) {
    __shared__ float As[8][128];
    __shared__ float Ws[8][128];
    const int tid = threadIdx.x;
    const int bm = blockIdx.y * 128;
    const int bn = blockIdx.x * 128;
    const int tx = tid & 15, ty = tid >> 4;
    float acc[8][8];
    #pragma unroll
    for (int i = 0; i < 8; i++)
        #pragma unroll
        for (int j = 0; j < 8; j++) acc[i][j] = 0.f;

    const int ra = tid >> 1, ka = (tid & 1) << 2;
    const int kw = tid >> 5, nw = (tid & 31) << 2;
    const int arow = bm + ra;

    for (int k0 = 0; k0 < K; k0 += 8) {
        float4 av;
        if (arow < M && (k0 + ka + 4) <= K) {
            av = *(const float4*)(A + (size_t)arow*K + k0 + ka);
        } else {
            av.x = (arow < M && k0+ka+0 < K) ? A[(size_t)arow*K + k0+ka+0] : 0.f;
            av.y = (arow < M && k0+ka+1 < K) ? A[(size_t)arow*K + k0+ka+1] : 0.f;
            av.z = (arow < M && k0+ka+2 < K) ? A[(size_t)arow*K + k0+ka+2] : 0.f;
            av.w = (arow < M && k0+ka+3 < K) ? A[(size_t)arow*K + k0+ka+3] : 0.f;
        }
        As[ka+0][ra] = av.x; As[ka+1][ra] = av.y;
        As[ka+2][ra] = av.z; As[ka+3][ra] = av.w;

        float4 wv;
        int wrow = k0 + kw;
        if (wrow < K && (bn + nw + 4) <= N) {
            wv = *(const float4*)(W + (size_t)wrow*N + bn + nw);
        } else {
            wv.x = (wrow < K && bn+nw+0 < N) ? W[(size_t)wrow*N + bn+nw+0] : 0.f;
            wv.y = (wrow < K && bn+nw+1 < N) ? W[(size_t)wrow*N + bn+nw+1] : 0.f;
            wv.z = (wrow < K && bn+nw+2 < N) ? W[(size_t)wrow*N + bn+nw+2] : 0.f;
            wv.w = (wrow < K && bn+nw+3 < N) ? W[(size_t)wrow*N + bn+nw+3] : 0.f;
        }
        *(float4*)(&Ws[kw][nw]) = wv;
        __syncthreads();

        #pragma unroll
        for (int kk = 0; kk < 8; kk++) {
            float4 a0 = *(const float4*)(&As[kk][ty*8]);
            float4 a1 = *(const float4*)(&As[kk][ty*8+4]);
            float4 b0 = *(const float4*)(&Ws[kk][tx*8]);
            float4 b1 = *(const float4*)(&Ws[kk][tx*8+4]);
            float ar[8] = {a0.x,a0.y,a0.z,a0.w,a1.x,a1.y,a1.z,a1.w};
            float br[8] = {b0.x,b0.y,b0.z,b0.w,b1.x,b1.y,b1.z,b1.w};
            #pragma unroll
            for (int i = 0; i < 8; i++)
                #pragma unroll
                for (int j = 0; j < 8; j++)
                    acc[i][j] = fmaf(ar[i], br[j], acc[i][j]);
        }
        __syncthreads();
    }

    #pragma unroll
    for (int i = 0; i < 8; i++) {
        int row = bm + ty*8 + i;
        if (row >= M) continue;
        #pragma unroll
        for (int j = 0; j < 8; j++) {
            int col = bn + tx*8 + j;
            if (col >= N) continue;
            float v = acc[i][j] + bias[col];
            if (EPI == 1) v = gelu_f(v);
            if (EPI == 2) v += Res[(size_t)row*N + col];
            C[(size_t)row*N + col] = v;
        }
    }
}

// -------- windowed attention: one block per (window, head) --------
__global__ void attn_kernel(const int* __restrict__ rpi, const float* __restrict__ rpb) {
    extern __shared__ float sm[];
    float* sQ = sm;                 // NQ*D_
    float* sK = sQ + NQ*D_;         // NK*D_
    float* sV = sK + NK*D_;         // NK*DV
    float* sP = sV + NK*DV;         // 8 warps * NK

    int blk  = blockIdx.x;
    int head = blk % NH_;
    int win  = blk / NH_;
    int wx = win % 16;
    int wy = (win / 16) % 16;
    int b  = win / 256;
    int tid = threadIdx.x;          // 256

    const float scale = rsqrtf((float)D_);
    for (int i = tid; i < NQ*D_; i += 256) {
        int qr = i / D_, d = i - qr*D_;
        int qy = qr >> 3, qx = qr & 7;
        sQ[i] = g_q[(((size_t)(b*H2 + wy*8+qy))*W2 + wx*8+qx)*C_ + head*D_ + d] * scale;
    }
    for (int i = tid; i < NK*D_; i += 256) {
        int kr = i / D_, d = i - kr*D_;
        int iy = kr / 12, ix = kr - iy*12;
        int y2 = wy*8 + iy - 4, x2 = wx*8 + ix - 4;
        float val = 0.f;
        if ((unsigned)y2 < (unsigned)H2 && (unsigned)x2 < (unsigned)W2)
            val = g_k[(((size_t)(b*H2 + y2))*W2 + x2)*C_ + head*D_ + d];
        sK[i] = val;
    }
    for (int i = tid; i < NK*DV; i += 256) {
        int kr = i / DV, d = i - kr*DV;
        int iy = kr / 12, ix = kr - iy*12;
        int y2 = wy*8 + iy - 4, x2 = wx*8 + ix - 4;
        float val = 0.f;
        if ((unsigned)y2 < (unsigned)H2 && (unsigned)x2 < (unsigned)W2)
            val = g_v[(((size_t)(b*H2 + y2))*W2 + x2)*C4 + head*DV + d];
        sV[i] = val;
    }
    __syncthreads();

    int warp = tid >> 5, lane = tid & 31;
    float* p = sP + warp*NK;
    for (int qr = warp; qr < NQ; qr += 8) {
        const float* qp = sQ + qr*D_;
        float s[5]; float mx = -1e30f;
        #pragma unroll
        for (int j = 0; j < 5; j++) {
            int kk = lane + j*32;
            float acc = -1e30f;
            if (kk < NK) {
                acc = rpb[rpi[qr*NK + kk]*NH_ + head];
                const float* kp = sK + kk*D_;
                #pragma unroll
                for (int d = 0; d < D_; d++) acc = fmaf(qp[d], kp[d], acc);
            }
            s[j] = acc; mx = fmaxf(mx, acc);
        }
        #pragma unroll
        for (int off = 16; off; off >>= 1)
            mx = fmaxf(mx, __shfl_xor_sync(0xffffffffu, mx, off));
        float sum = 0.f;
        #pragma unroll
        for (int j = 0; j < 5; j++) {
            int kk = lane + j*32;
            float e = (kk < NK) ? __expf(s[j] - mx) : 0.f;
            s[j] = e; sum += e;
        }
        #pragma unroll
        for (int off = 16; off; off >>= 1)
            sum += __shfl_xor_sync(0xffffffffu, sum, off);
        float inv = 1.0f / sum;
        #pragma unroll
        for (int j = 0; j < 5; j++) {
            int kk = lane + j*32;
            if (kk < NK) p[kk] = s[j]*inv;
        }
        __syncwarp();
        if (lane < 30) {
            float4 o4 = make_float4(0.f, 0.f, 0.f, 0.f);
            #pragma unroll 4
            for (int kk = 0; kk < NK; kk++) {
                float pk = p[kk];
                float4 v4 = *(const float4*)(sV + kk*DV + lane*4);
                o4.x = fmaf(pk, v4.x, o4.x);
                o4.y = fmaf(pk, v4.y, o4.y);
                o4.z = fmaf(pk, v4.z, o4.z);
                o4.w = fmaf(pk, v4.w, o4.w);
            }
            int qy = qr >> 3, qx = qr & 7;
            float* outp = g_o + (((size_t)(b*H2 + wy*8+qy))*W2 + wx*8+qx)*C4
                              + head*DV + lane*4;
            *(float4*)outp = o4;
        }
        __syncwarp();
    }
}

// -------- inverse DWT: g_o (b,128,128,720) -> g_xr (b,256,256,180) --------
__global__ void idwt_kernel() {
    int idx = blockIdx.x * blockDim.x + threadIdx.x;
    if (idx >= NPOS2 * C_) return;
    int c   = idx % C_;
    int pos = idx / C_;
    int x2 = pos & 127; int t = pos >> 7;
    int y2 = t & 127;   int b = t >> 7;
    const float* op = g_o + (size_t)pos*C4 + c;
    float ll = op[0], lh = op[C_], hl = op[2*C_], hh = op[3*C_];
    float a  = (ll - lh - hl + hh)*0.5f;
    float bb = (ll - lh + hl - hh)*0.5f;
    float cc = (ll + lh - hl - hh)*0.5f;
    float dd = (ll + lh + hl + hh)*0.5f;
    float* base = g_xr + (((size_t)(b*HH + 2*y2))*WWF + 2*x2)*C_ + c;
    base[0]                 = a;
    base[C_]                = bb;
    base[(size_t)WWF*C_]      = cc;
    base[(size_t)WWF*C_ + C_] = dd;
}

// -------- LayerNorm2 (warp per token): g_x1 -> g_ln --------
__global__ void ln2_kernel(const float* __restrict__ w, const float* __restrict__ bias) {
    int gw   = (blockIdx.x * blockDim.x + threadIdx.x) >> 5;
    int lane = threadIdx.x & 31;
    if (gw >= NTOK) return;
    const float* row = g_x1 + (size_t)gw*C_;
    float v[6]; float s = 0.f, ss = 0.f;
    #pragma unroll
    for (int j = 0; j < 6; j++) {
        int c = lane + j*32;
        float val = (c < C_) ? row[c] : 0.f;
        v[j] = val; s += val; ss = fmaf(val, val, ss);
    }
    #pragma unroll
    for (int off = 16; off; off >>= 1) {
        s  += __shfl_xor_sync(0xffffffffu, s,  off);
        ss += __shfl_xor_sync(0xffffffffu, ss, off);
    }
    float mu  = s * (1.0f/(float)C_);
    float var = ss * (1.0f/(float)C_) - mu*mu;
    float r   = rsqrtf(var + 1e-5f);
    float* orow = g_ln + (size_t)gw*C_;
    #pragma unroll
    for (int j = 0; j < 6; j++) {
        int c = lane + j*32;
        if (c < C_) orow[c] = (v[j] - mu)*r*w[c] + bias[c];
    }
}

extern "C" void kernel_launch(void* const* d_in, const int* in_sizes, int n_in,
                              void* d_out, int out_size) {
    const float* x   = (const float*)d_in[0];
    const int*   rpi = (const int*)  d_in[2];
    const float* n1w = (const float*)d_in[5];
    const float* n1b = (const float*)d_in[6];
    const float* qw  = (const float*)d_in[9];
    const float* qb  = (const float*)d_in[10];
    const float* kw_ = (const float*)d_in[11];
    const float* kb  = (const float*)d_in[12];
    const float* vw  = (const float*)d_in[13];
    const float* vb  = (const float*)d_in[14];
    const float* rpb = (const float*)d_in[15];
    const float* pw  = (const float*)d_in[16];
    const float* pb  = (const float*)d_in[17];
    const float* n2w = (const float*)d_in[18];
    const float* n2b = (const float*)d_in[19];
    const float* f1w = (const float*)d_in[20];
    const float* f1b = (const float*)d_in[21];
    const float* f2w = (const float*)d_in[22];
    const float* f2b = (const float*)d_in[23];
    float* out = (float*)d_out;

    float *p_xd, *p_q, *p_k, *p_v, *p_xr, *p_x1, *p_ln, *p_h;
    cudaGetSymbolAddress((void**)&p_xd, g_xd);
    cudaGetSymbolAddress((void**)&p_q,  g_q);
    cudaGetSymbolAddress((void**)&p_k,  g_k);
    cudaGetSymbolAddress((void**)&p_v,  g_v);
    cudaGetSymbolAddress((void**)&p_xr, g_xr);
    cudaGetSymbolAddress((void**)&p_x1, g_x1);
    cudaGetSymbolAddress((void**)&p_ln, g_ln);
    cudaGetSymbolAddress((void**)&p_h,  g_h);

    // 1) LN(norm1) + DWT -> g_xd
    ln_dwt_kernel<<<NPOS2, 192>>>(x, n1w, n1b);

    // 2,3) q,k projections
    {
        dim3 g((C_ + 127)/128, (NPOS2 + 127)/128);
        sgemm_kernel<0><<<g, 256>>>(p_xd, qw,  qb, nullptr, p_q, NPOS2, C_, C4);
        sgemm_kernel<0><<<g, 256>>>(p_xd, kw_, kb, nullptr, p_k, NPOS2, C_, C4);
    }
    // 4) v projection
    {
        dim3 g((C4 + 127)/128, (NPOS2 + 127)/128);
        sgemm_kernel<0><<<g, 256>>>(p_xd, vw, vb, nullptr, p_v, NPOS2, C4, C4);
    }
    // 5) windowed attention -> g_o
    cudaFuncSetAttribute(attn_kernel, cudaFuncAttributeMaxDynamicSharedMemorySize, ATTN_SMEM);
    attn_kernel<<<NWIN*NH_, 256, ATTN_SMEM>>>(rpi, rpb);

    // 6) inverse DWT -> g_xr
    idwt_kernel<<<(NPOS2*C_ + 255)/256, 256>>>();

    // 7) proj + residual -> g_x1
    {
        dim3 g((C_ + 127)/128, (NTOK + 127)/128);
        sgemm_kernel<2><<<g, 256>>>(p_xr, pw, pb, x, p_x1, NTOK, C_, C_);
    }
    // 8) LN(norm2) -> g_ln
    ln2_kernel<<<NTOK/8, 256>>>(n2w, n2b);

    // 9) fc1 + gelu -> g_h
    {
        dim3 g((2*C_ + 127)/128, (NTOK + 127)/128);
        sgemm_kernel<1><<<g, 256>>>(p_ln, f1w, f1b, nullptr, p_h, NTOK, 2*C_, C_);
    }
    // 10) fc2 + residual(g_x1) -> out
    {
        dim3 g((C_ + 127)/128, (NTOK + 127)/128);
        sgemm_kernel<2><<<g, 256>>>(p_h, f2w, f2b, p_x1, out, NTOK, C_, 2*C_);
    }
}

// round 2
// speedup vs baseline: 2.3372x; 2.3372x over previous
#include <cuda_runtime.h>
#include <cuda_bf16.h>
#include <math.h>
#include <stdint.h>

// Problem constants
#define B_    2
#define HH    256
#define WWF   256
#define C_    180
#define C4    720
#define H2    128
#define W2    128
#define NH_   6
#define D_    30
#define DV    120
#define NQ    64
#define NK    144
#define NWIN  512
#define NPOS2 (B_*H2*W2)     // 32768
#define NTOK  (B_*HH*WWF)    // 131072

#define ATTN_SMEM ((NQ*D_ + NK*D_ + NK*DV + 8*NK) * 4)  // 98688 B

// -------- scratch (device globals; no allocation) --------
__device__ __align__(256) float g_xd[(size_t)NPOS2*C4];
__device__ __align__(256) float g_q [(size_t)NPOS2*C_];
__device__ __align__(256) float g_k [(size_t)NPOS2*C_];
__device__ __align__(256) float g_v [(size_t)NPOS2*C4];
__device__ __align__(256) float g_o [(size_t)NPOS2*C4];
__device__ __align__(256) float g_xr[(size_t)NTOK*C_];
__device__ __align__(256) float g_x1[(size_t)NTOK*C_];
__device__ __align__(256) float g_ln[(size_t)NTOK*C_];
__device__ __align__(256) float g_h [(size_t)NTOK*2*C_];

__device__ __forceinline__ float gelu_f(float x) {
    return 0.5f * x * (1.0f + erff(x * 0.70710678118654752440f));
}

__device__ __forceinline__ uint32_t f2tf32(float f) {
    uint32_t u;
    asm("cvt.rna.tf32.f32 %0, %1;" : "=r"(u) : "f"(f));
    return u;
}

// -------- LayerNorm + DWT fused: one block per (b,y2,x2) --------
__global__ void ln_dwt_kernel(const float* __restrict__ x,
                              const float* __restrict__ w,
                              const float* __restrict__ bias) {
    __shared__ float red[6][8];
    int pos = blockIdx.x;                 // 0..NPOS2-1
    int x2 = pos & 127; int t = pos >> 7;
    int y2 = t & 127;   int b = t >> 7;
    int tid = threadIdx.x;                // 192 threads
    const float* p00 = x + (((size_t)(b*HH + 2*y2))*WWF + 2*x2)*C_;
    float a=0.f, bv=0.f, cv=0.f, dv=0.f;
    if (tid < C_) {
        a  = p00[tid];
        bv = p00[C_ + tid];
        cv = p00[(size_t)WWF*C_ + tid];
        dv = p00[(size_t)WWF*C_ + C_ + tid];
    }
    float q0=a, q1=bv, q2=cv, q3=dv, q4=a*a, q5=bv*bv, q6=cv*cv, q7=dv*dv;
    #pragma unroll
    for (int off = 16; off; off >>= 1) {
        q0 += __shfl_xor_sync(0xffffffffu, q0, off);
        q1 += __shfl_xor_sync(0xffffffffu, q1, off);
        q2 += __shfl_xor_sync(0xffffffffu, q2, off);
        q3 += __shfl_xor_sync(0xffffffffu, q3, off);
        q4 += __shfl_xor_sync(0xffffffffu, q4, off);
        q5 += __shfl_xor_sync(0xffffffffu, q5, off);
        q6 += __shfl_xor_sync(0xffffffffu, q6, off);
        q7 += __shfl_xor_sync(0xffffffffu, q7, off);
    }
    int lane = tid & 31, warp = tid >> 5;
    if (lane == 0) {
        red[warp][0]=q0; red[warp][1]=q1; red[warp][2]=q2; red[warp][3]=q3;
        red[warp][4]=q4; red[warp][5]=q5; red[warp][6]=q6; red[warp][7]=q7;
    }
    __syncthreads();
    float s[8];
    #pragma unroll
    for (int i = 0; i < 8; i++) {
        float acc = 0.f;
        #pragma unroll
        for (int wv = 0; wv < 6; wv++) acc += red[wv][i];
        s[i] = acc;
    }
    if (tid < C_) {
        const float inv = 1.0f / (float)C_;
        float mu0=s[0]*inv, mu1=s[1]*inv, mu2=s[2]*inv, mu3=s[3]*inv;
        float r0 = rsqrtf(s[4]*inv - mu0*mu0 + 1e-5f);
        float r1 = rsqrtf(s[5]*inv - mu1*mu1 + 1e-5f);
        float r2 = rsqrtf(s[6]*inv - mu2*mu2 + 1e-5f);
        float r3 = rsqrtf(s[7]*inv - mu3*mu3 + 1e-5f);
        float ww = w[tid], wb = bias[tid];
        float an = (a  - mu0)*r0*ww + wb;
        float bn = (bv - mu1)*r1*ww + wb;
        float cn = (cv - mu2)*r2*ww + wb;
        float dn = (dv - mu3)*r3*ww + wb;
        float* outp = g_xd + (size_t)pos*C4;
        outp[tid]        = ( an + bn + cn + dn)*0.5f;  // ll
        outp[C_   + tid] = (-an - bn + cn + dn)*0.5f;  // lh
        outp[2*C_ + tid] = (-an + bn - cn + dn)*0.5f;  // hl
        outp[3*C_ + tid] = ( an - bn - cn + dn)*0.5f;  // hh
    }
}

// ======== tf32 tensor-core GEMM: C = A(MxK) @ W(KxN) + bias [+epi] ========
// BM=128, BN=96, BK=16, 256 threads (8 warps: 2 in M x 4 in N; warp tile 64x24)
// EPI: 0 = bias only, 1 = gelu(bias+acc), 2 = bias+acc+Res
// Requires: M % 128 == 0, K % 4 == 0, N % 4 == 0, N even.
#define MMA_TF32(d, a, b) \
    asm volatile("mma.sync.aligned.m16n8k8.row.col.f32.tf32.tf32.f32 " \
        "{%0,%1,%2,%3},{%4,%5,%6,%7},{%8,%9},{%0,%1,%2,%3};" \
        : "+f"(d[0]), "+f"(d[1]), "+f"(d[2]), "+f"(d[3]) \
        : "r"(a[0]), "r"(a[1]), "r"(a[2]), "r"(a[3]), "r"(b[0]), "r"(b[1]))

template<int EPI>
__global__ void __launch_bounds__(256, 2)
tf32gemm_kernel(const float* __restrict__ A, const float* __restrict__ W,
                const float* __restrict__ bias, const float* __restrict__ Res,
                float* __restrict__ C, int M, int N, int K) {
    __shared__ uint32_t As[128 * 20];   // [m][k], k-stride 20 (16 + pad4): frag-load conflict-free
    __shared__ uint32_t Bs[16 * 104];   // [k][n], n-stride 104 (96 + pad8): frag-load conflict-free

    const int tid  = threadIdx.x;
    const int bm   = blockIdx.y * 128;
    const int bn   = blockIdx.x * 96;
    const int lane = tid & 31;
    const int warp = tid >> 5;
    const int wm   = (warp & 1) * 64;      // warp row offset in tile
    const int wn   = (warp >> 1) * 24;     // warp col offset in tile
    const int lq   = lane >> 2;            // 0..7
    const int lr   = lane & 3;             // 0..3

    float acc[4][3][4];
    #pragma unroll
    for (int i = 0; i < 4; i++)
        #pragma unroll
        for (int j = 0; j < 3; j++)
            #pragma unroll
            for (int r = 0; r < 4; r++) acc[i][j][r] = 0.f;

    // A prefetch slots: float4 ids {tid, tid+256} over 512 f4 = 128 rows x 4
    const int a_row0 = tid >> 2;           // id = tid
    const int a_kq0  = tid & 3;
    const int a_row1 = (tid + 256) >> 2;   // id = tid+256
    const int a_kq1  = (tid + 256) & 3;
    // B prefetch slots: float4 ids {tid, tid+256 (if tid<128)} over 384 f4 = 16 k x 24
    const int b_k0 = tid / 24, b_n0 = (tid % 24) * 4;
    const int b_id1 = tid + 256;
    const int b_k1 = b_id1 / 24, b_n1 = (b_id1 % 24) * 4;
    const bool b_has1 = (b_id1 < 384);

    float4 aP[2], bP[2];

    const int niter = (K + 15) >> 4;

    // ---- prefetch k0 = 0 ----
    {
        const int k0 = 0;
        int gk;
        gk = k0 + a_kq0 * 4;
        aP[0] = (gk < K) ? *(const float4*)(A + (size_t)(bm + a_row0)*K + gk)
                         : make_float4(0.f,0.f,0.f,0.f);
        gk = k0 + a_kq1 * 4;
        aP[1] = (gk < K) ? *(const float4*)(A + (size_t)(bm + a_row1)*K + gk)
                         : make_float4(0.f,0.f,0.f,0.f);
        gk = k0 + b_k0;
        bP[0] = (gk < K && bn + b_n0 < N) ? *(const float4*)(W + (size_t)gk*N + bn + b_n0)
                                          : make_float4(0.f,0.f,0.f,0.f);
        gk = k0 + b_k1;
        bP[1] = (b_has1 && gk < K && bn + b_n1 < N) ? *(const float4*)(W + (size_t)gk*N + bn + b_n1)
                                                    : make_float4(0.f,0.f,0.f,0.f);
    }

    for (int it = 0; it < niter; it++) {
        __syncthreads();   // previous compute done before overwriting smem
        // store prefetched tile to smem (tf32-converted)
        {
            uint4 u;
            u.x = f2tf32(aP[0].x); u.y = f2tf32(aP[0].y);
            u.z = f2tf32(aP[0].z); u.w = f2tf32(aP[0].w);
            *(uint4*)&As[a_row0*20 + a_kq0*4] = u;
            u.x = f2tf32(aP[1].x); u.y = f2tf32(aP[1].y);
            u.z = f2tf32(aP[1].z); u.w = f2tf32(aP[1].w);
            *(uint4*)&As[a_row1*20 + a_kq1*4] = u;
            u.x = f2tf32(bP[0].x); u.y = f2tf32(bP[0].y);
            u.z = f2tf32(bP[0].z); u.w = f2tf32(bP[0].w);
            *(uint4*)&Bs[b_k0*104 + b_n0] = u;
            if (b_has1) {
                u.x = f2tf32(bP[1].x); u.y = f2tf32(bP[1].y);
                u.z = f2tf32(bP[1].z); u.w = f2tf32(bP[1].w);
                *(uint4*)&Bs[b_k1*104 + b_n1] = u;
            }
        }
        __syncthreads();

        // prefetch next tile (overlaps with MMA below)
        if (it + 1 < niter) {
            const int k0 = (it + 1) * 16;
            int gk;
            gk = k0 + a_kq0 * 4;
            aP[0] = (gk < K) ? *(const float4*)(A + (size_t)(bm + a_row0)*K + gk)
                             : make_float4(0.f,0.f,0.f,0.f);
            gk = k0 + a_kq1 * 4;
            aP[1] = (gk < K) ? *(const float4*)(A + (size_t)(bm + a_row1)*K + gk)
                             : make_float4(0.f,0.f,0.f,0.f);
            gk = k0 + b_k0;
            bP[0] = (gk < K && bn + b_n0 < N) ? *(const float4*)(W + (size_t)gk*N + bn + b_n0)
                                              : make_float4(0.f,0.f,0.f,0.f);
            gk = k0 + b_k1;
            bP[1] = (b_has1 && gk < K && bn + b_n1 < N) ? *(const float4*)(W + (size_t)gk*N + bn + b_n1)
                                                        : make_float4(0.f,0.f,0.f,0.f);
        }

        // compute: 2 k-steps of 8
        #pragma unroll
        for (int ks = 0; ks < 2; ks++) {
            const int kb = ks * 8;
            uint32_t af[4][4], bf[3][2];
            #pragma unroll
            for (int mt = 0; mt < 4; mt++) {
                const int base = wm + mt*16;
                af[mt][0] = As[(base + lq    )*20 + kb + lr    ];
                af[mt][1] = As[(base + lq + 8)*20 + kb + lr    ];
                af[mt][2] = As[(base + lq    )*20 + kb + lr + 4];
                af[mt][3] = As[(base + lq + 8)*20 + kb + lr + 4];
            }
            #pragma unroll
            for (int nt = 0; nt < 3; nt++) {
                const int nb = wn + nt*8 + lq;
                bf[nt][0] = Bs[(kb + lr    )*104 + nb];
                bf[nt][1] = Bs[(kb + lr + 4)*104 + nb];
            }
            #pragma unroll
            for (int mt = 0; mt < 4; mt++)
                #pragma unroll
                for (int nt = 0; nt < 3; nt++)
                    MMA_TF32(acc[mt][nt], af[mt], bf[nt]);
        }
    }

    // ---- epilogue ----
    #pragma unroll
    for (int mt = 0; mt < 4; mt++) {
        const int row0 = bm + wm + mt*16 + lq;
        const int row1 = row0 + 8;
        #pragma unroll
        for (int nt = 0; nt < 3; nt++) {
            const int col = bn + wn + nt*8 + 2*lr;
            if (col >= N) continue;     // N even, col even -> col+1 < N too
            const float b0 = bias[col], b1 = bias[col + 1];
            float v0 = acc[mt][nt][0] + b0;
            float v1 = acc[mt][nt][1] + b1;
            float v2 = acc[mt][nt][2] + b0;
            float v3 = acc[mt][nt][3] + b1;
            if (EPI == 1) {
                v0 = gelu_f(v0); v1 = gelu_f(v1);
                v2 = gelu_f(v2); v3 = gelu_f(v3);
            }
            if (EPI == 2) {
                const float* r0p = Res + (size_t)row0*N + col;
                const float* r1p = Res + (size_t)row1*N + col;
                v0 += r0p[0]; v1 += r0p[1];
                v2 += r1p[0]; v3 += r1p[1];
            }
            *(float2*)(C + (size_t)row0*N + col) = make_float2(v0, v1);
            *(float2*)(C + (size_t)row1*N + col) = make_float2(v2, v3);
        }
    }
}

// -------- windowed attention: one block per (window, head) --------
__global__ void attn_kernel(const int* __restrict__ rpi, const float* __restrict__ rpb) {
    extern __shared__ float sm[];
    float* sQ = sm;                 // NQ*D_
    float* sK = sQ + NQ*D_;         // NK*D_
    float* sV = sK + NK*D_;         // NK*DV
    float* sP = sV + NK*DV;         // 8 warps * NK

    int blk  = blockIdx.x;
    int head = blk % NH_;
    int win  = blk / NH_;
    int wx = win % 16;
    int wy = (win / 16) % 16;
    int b  = win / 256;
    int tid = threadIdx.x;          // 256

    const float scale = rsqrtf((float)D_);
    for (int i = tid; i < NQ*D_; i += 256) {
        int qr = i / D_, d = i - qr*D_;
        int qy = qr >> 3, qx = qr & 7;
        sQ[i] = g_q[(((size_t)(b*H2 + wy*8+qy))*W2 + wx*8+qx)*C_ + head*D_ + d] * scale;
    }
    for (int i = tid; i < NK*D_; i += 256) {
        int kr = i / D_, d = i - kr*D_;
        int iy = kr / 12, ix = kr - iy*12;
        int y2 = wy*8 + iy - 4, x2 = wx*8 + ix - 4;
        float val = 0.f;
        if ((unsigned)y2 < (unsigned)H2 && (unsigned)x2 < (unsigned)W2)
            val = g_k[(((size_t)(b*H2 + y2))*W2 + x2)*C_ + head*D_ + d];
        sK[i] = val;
    }
    for (int i = tid; i < NK*DV; i += 256) {
        int kr = i / DV, d = i - kr*DV;
        int iy = kr / 12, ix = kr - iy*12;
        int y2 = wy*8 + iy - 4, x2 = wx*8 + ix - 4;
        float val = 0.f;
        if ((unsigned)y2 < (unsigned)H2 && (unsigned)x2 < (unsigned)W2)
            val = g_v[(((size_t)(b*H2 + y2))*W2 + x2)*C4 + head*DV + d];
        sV[i] = val;
    }
    __syncthreads();

    int warp = tid >> 5, lane = tid & 31;
    float* p = sP + warp*NK;
    for (int qr = warp; qr < NQ; qr += 8) {
        const float* qp = sQ + qr*D_;
        float s[5]; float mx = -1e30f;
        #pragma unroll
        for (int j = 0; j < 5; j++) {
            int kk = lane + j*32;
            float acc = -1e30f;
            if (kk < NK) {
                acc = rpb[rpi[qr*NK + kk]*NH_ + head];
                const float* kp = sK + kk*D_;
                #pragma unroll
                for (int d = 0; d < D_; d++) acc = fmaf(qp[d], kp[d], acc);
            }
            s[j] = acc; mx = fmaxf(mx, acc);
        }
        #pragma unroll
        for (int off = 16; off; off >>= 1)
            mx = fmaxf(mx, __shfl_xor_sync(0xffffffffu, mx, off));
        float sum = 0.f;
        #pragma unroll
        for (int j = 0; j < 5; j++) {
            int kk = lane + j*32;
            float e = (kk < NK) ? __expf(s[j] - mx) : 0.f;
            s[j] = e; sum += e;
        }
        #pragma unroll
        for (int off = 16; off; off >>= 1)
            sum += __shfl_xor_sync(0xffffffffu, sum, off);
        float inv = 1.0f / sum;
        #pragma unroll
        for (int j = 0; j < 5; j++) {
            int kk = lane + j*32;
            if (kk < NK) p[kk] = s[j]*inv;
        }
        __syncwarp();
        if (lane < 30) {
            float4 o4 = make_float4(0.f, 0.f, 0.f, 0.f);
            #pragma unroll 4
            for (int kk = 0; kk < NK; kk++) {
                float pk = p[kk];
                float4 v4 = *(const float4*)(sV + kk*DV + lane*4);
                o4.x = fmaf(pk, v4.x, o4.x);
                o4.y = fmaf(pk, v4.y, o4.y);
                o4.z = fmaf(pk, v4.z, o4.z);
                o4.w = fmaf(pk, v4.w, o4.w);
            }
            int qy = qr >> 3, qx = qr & 7;
            float* outp = g_o + (((size_t)(b*H2 + wy*8+qy))*W2 + wx*8+qx)*C4
                              + head*DV + lane*4;
            *(float4*)outp = o4;
        }
        __syncwarp();
    }
}

// -------- inverse DWT: g_o (b,128,128,720) -> g_xr (b,256,256,180) --------
__global__ void idwt_kernel() {
    int idx = blockIdx.x * blockDim.x + threadIdx.x;
    if (idx >= NPOS2 * C_) return;
    int c   = idx % C_;
    int pos = idx / C_;
    int x2 = pos & 127; int t = pos >> 7;
    int y2 = t & 127;   int b = t >> 7;
    const float* op = g_o + (size_t)pos*C4 + c;
    float ll = op[0], lh = op[C_], hl = op[2*C_], hh = op[3*C_];
    float a  = (ll - lh - hl + hh)*0.5f;
    float bb = (ll - lh + hl - hh)*0.5f;
    float cc = (ll + lh - hl - hh)*0.5f;
    float dd = (ll + lh + hl + hh)*0.5f;
    float* base = g_xr + (((size_t)(b*HH + 2*y2))*WWF + 2*x2)*C_ + c;
    base[0]                 = a;
    base[C_]                = bb;
    base[(size_t)WWF*C_]      = cc;
    base[(size_t)WWF*C_ + C_] = dd;
}

// -------- LayerNorm2 (warp per token): g_x1 -> g_ln --------
__global__ void ln2_kernel(const float* __restrict__ w, const float* __restrict__ bias) {
    int gw   = (blockIdx.x * blockDim.x + threadIdx.x) >> 5;
    int lane = threadIdx.x & 31;
    if (gw >= NTOK) return;
    const float* row = g_x1 + (size_t)gw*C_;
    float v[6]; float s = 0.f, ss = 0.f;
    #pragma unroll
    for (int j = 0; j < 6; j++) {
        int c = lane + j*32;
        float val = (c < C_) ? row[c] : 0.f;
        v[j] = val; s += val; ss = fmaf(val, val, ss);
    }
    #pragma unroll
    for (int off = 16; off; off >>= 1) {
        s  += __shfl_xor_sync(0xffffffffu, s,  off);
        ss += __shfl_xor_sync(0xffffffffu, ss, off);
    }
    float mu  = s * (1.0f/(float)C_);
    float var = ss * (1.0f/(float)C_) - mu*mu;
    float r   = rsqrtf(var + 1e-5f);
    float* orow = g_ln + (size_t)gw*C_;
    #pragma unroll
    for (int j = 0; j < 6; j++) {
        int c = lane + j*32;
        if (c < C_) orow[c] = (v[j] - mu)*r*w[c] + bias[c];
    }
}

extern "C" void kernel_launch(void* const* d_in, const int* in_sizes, int n_in,
                              void* d_out, int out_size) {
    const float* x   = (const float*)d_in[0];
    const int*   rpi = (const int*)  d_in[2];
    const float* n1w = (const float*)d_in[5];
    const float* n1b = (const float*)d_in[6];
    const float* qw  = (const float*)d_in[9];
    const float* qb  = (const float*)d_in[10];
    const float* kw_ = (const float*)d_in[11];
    const float* kb  = (const float*)d_in[12];
    const float* vw  = (const float*)d_in[13];
    const float* vb  = (const float*)d_in[14];
    const float* rpb = (const float*)d_in[15];
    const float* pw  = (const float*)d_in[16];
    const float* pb  = (const float*)d_in[17];
    const float* n2w = (const float*)d_in[18];
    const float* n2b = (const float*)d_in[19];
    const float* f1w = (const float*)d_in[20];
    const float* f1b = (const float*)d_in[21];
    const float* f2w = (const float*)d_in[22];
    const float* f2b = (const float*)d_in[23];
    float* out = (float*)d_out;

    float *p_xd, *p_q, *p_k, *p_v, *p_xr, *p_x1, *p_ln, *p_h;
    cudaGetSymbolAddress((void**)&p_xd, g_xd);
    cudaGetSymbolAddress((void**)&p_q,  g_q);
    cudaGetSymbolAddress((void**)&p_k,  g_k);
    cudaGetSymbolAddress((void**)&p_v,  g_v);
    cudaGetSymbolAddress((void**)&p_xr, g_xr);
    cudaGetSymbolAddress((void**)&p_x1, g_x1);
    cudaGetSymbolAddress((void**)&p_ln, g_ln);
    cudaGetSymbolAddress((void**)&p_h,  g_h);

    // 1) LN(norm1) + DWT -> g_xd
    ln_dwt_kernel<<<NPOS2, 192>>>(x, n1w, n1b);

    // 2,3) q,k projections (M=32768, N=180, K=720)
    {
        dim3 g((C_ + 95)/96, NPOS2/128);
        tf32gemm_kernel<0><<<g, 256>>>(p_xd, qw,  qb, nullptr, p_q, NPOS2, C_, C4);
        tf32gemm_kernel<0><<<g, 256>>>(p_xd, kw_, kb, nullptr, p_k, NPOS2, C_, C4);
    }
    // 4) v projection (M=32768, N=720, K=720)
    {
        dim3 g((C4 + 95)/96, NPOS2/128);
        tf32gemm_kernel<0><<<g, 256>>>(p_xd, vw, vb, nullptr, p_v, NPOS2, C4, C4);
    }
    // 5) windowed attention -> g_o
    cudaFuncSetAttribute(attn_kernel, cudaFuncAttributeMaxDynamicSharedMemorySize, ATTN_SMEM);
    attn_kernel<<<NWIN*NH_, 256, ATTN_SMEM>>>(rpi, rpb);

    // 6) inverse DWT -> g_xr
    idwt_kernel<<<(NPOS2*C_ + 255)/256, 256>>>();

    // 7) proj + residual -> g_x1 (M=131072, N=180, K=180)
    {
        dim3 g((C_ + 95)/96, NTOK/128);
        tf32gemm_kernel<2><<<g, 256>>>(p_xr, pw, pb, x, p_x1, NTOK, C_, C_);
    }
    // 8) LN(norm2) -> g_ln
    ln2_kernel<<<NTOK/8, 256>>>(n2w, n2b);

    // 9) fc1 + gelu -> g_h (M=131072, N=360, K=180)
    {
        dim3 g((2*C_ + 95)/96, NTOK/128);
        tf32gemm_kernel<1><<<g, 256>>>(p_ln, f1w, f1b, nullptr, p_h, NTOK, 2*C_, C_);
    }
    // 10) fc2 + residual(g_x1) -> out (M=131072, N=180, K=360)
    {
        dim3 g((C_ + 95)/96, NTOK/128);
        tf32gemm_kernel<2><<<g, 256>>>(p_h, f2w, f2b, p_x1, out, NTOK, C_, 2*C_);
    }
}

// round 16
// speedup vs baseline: 3.9074x; 1.6718x over previous
#include <cuda_runtime.h>
#include <cuda_bf16.h>
#include <math.h>
#include <stdint.h>

// Problem constants
#define B_    2
#define HH    256
#define WWF   256
#define C_    180
#define C4    720
#define H2    128
#define W2    128
#define NH_   6
#define D_    30
#define DV    120
#define NQ    64
#define NK    144
#define NWIN  512
#define NPOS2 (B_*H2*W2)     // 32768
#define NTOK  (B_*HH*WWF)    // 131072

// padded K strides (multiples of 32)
#define KP720 736
#define KP180 192
#define KP360 384

typedef __nv_bfloat16 bf16;

// -------- scratch (device globals; no allocation) --------
__device__ __align__(256) bf16  g_xdh[(size_t)NPOS2*KP720];  // LN+DWT out (bf16, padded)
__device__ __align__(256) float g_q  [(size_t)NPOS2*C_];
__device__ __align__(256) float g_k  [(size_t)NPOS2*C_];
__device__ __align__(256) bf16  g_vh [(size_t)NPOS2*KP720];  // v proj out (bf16, padded)
__device__ __align__(256) float g_o  [(size_t)NPOS2*C4];
__device__ __align__(256) bf16  g_xrh[(size_t)NTOK*KP180];   // idwt out (bf16, padded)
__device__ __align__(256) float g_x1 [(size_t)NTOK*C_];
__device__ __align__(256) bf16  g_lnh[(size_t)NTOK*KP180];   // ln2 out (bf16, padded)
__device__ __align__(256) bf16  g_hh [(size_t)NTOK*KP360];   // fc1 out (bf16, padded)

// transposed bf16 weights [Nt][Kp]
__device__ __align__(256) bf16 g_wtq [192*KP720];
__device__ __align__(256) bf16 g_wtk [192*KP720];
__device__ __align__(256) bf16 g_wtv [768*KP720];
__device__ __align__(256) bf16 g_wtp [192*KP180];
__device__ __align__(256) bf16 g_wtf1[384*KP180];
__device__ __align__(256) bf16 g_wtf2[192*KP360];

__device__ __forceinline__ float gelu_f(float x) {
    return 0.5f * x * (1.0f + erff(x * 0.70710678118654752440f));
}

// -------- weight prep: W[K][N] fp32 -> Wt[Nt][Kp] bf16 (transposed, zero-padded) --------
__global__ void wprep_kernel(const float* __restrict__ W, bf16* __restrict__ Wt,
                             int K, int N, int Kp, int Nt) {
    int idx = blockIdx.x * blockDim.x + threadIdx.x;
    if (idx >= Nt * Kp) return;
    int n = idx / Kp, k = idx - n * Kp;
    float v = (n < N && k < K) ? W[(size_t)k * N + n] : 0.f;
    Wt[idx] = __float2bfloat16_rn(v);
}

// -------- LayerNorm + DWT fused: one block per (b,y2,x2); bf16 out --------
__global__ void ln_dwt_kernel(const float* __restrict__ x,
                              const float* __restrict__ w,
                              const float* __restrict__ bias) {
    __shared__ float red[6][8];
    int pos = blockIdx.x;
    int x2 = pos & 127; int t = pos >> 7;
    int y2 = t & 127;   int b = t >> 7;
    int tid = threadIdx.x;                // 192 threads
    const float* p00 = x + (((size_t)(b*HH + 2*y2))*WWF + 2*x2)*C_;
    float a=0.f, bv=0.f, cv=0.f, dv=0.f;
    if (tid < C_) {
        a  = p00[tid];
        bv = p00[C_ + tid];
        cv = p00[(size_t)WWF*C_ + tid];
        dv = p00[(size_t)WWF*C_ + C_ + tid];
    }
    float q0=a, q1=bv, q2=cv, q3=dv, q4=a*a, q5=bv*bv, q6=cv*cv, q7=dv*dv;
    #pragma unroll
    for (int off = 16; off; off >>= 1) {
        q0 += __shfl_xor_sync(0xffffffffu, q0, off);
        q1 += __shfl_xor_sync(0xffffffffu, q1, off);
        q2 += __shfl_xor_sync(0xffffffffu, q2, off);
        q3 += __shfl_xor_sync(0xffffffffu, q3, off);
        q4 += __shfl_xor_sync(0xffffffffu, q4, off);
        q5 += __shfl_xor_sync(0xffffffffu, q5, off);
        q6 += __shfl_xor_sync(0xffffffffu, q6, off);
        q7 += __shfl_xor_sync(0xffffffffu, q7, off);
    }
    int lane = tid & 31, warp = tid >> 5;
    if (lane == 0) {
        red[warp][0]=q0; red[warp][1]=q1; red[warp][2]=q2; red[warp][3]=q3;
        red[warp][4]=q4; red[warp][5]=q5; red[warp][6]=q6; red[warp][7]=q7;
    }
    __syncthreads();
    float s[8];
    #pragma unroll
    for (int i = 0; i < 8; i++) {
        float acc = 0.f;
        #pragma unroll
        for (int wv = 0; wv < 6; wv++) acc += red[wv][i];
        s[i] = acc;
    }
    bf16* outp = g_xdh + (size_t)pos*KP720;
    if (tid < C_) {
        const float inv = 1.0f / (float)C_;
        float mu0=s[0]*inv, mu1=s[1]*inv, mu2=s[2]*inv, mu3=s[3]*inv;
        float r0 = rsqrtf(s[4]*inv - mu0*mu0 + 1e-5f);
        float r1 = rsqrtf(s[5]*inv - mu1*mu1 + 1e-5f);
        float r2 = rsqrtf(s[6]*inv - mu2*mu2 + 1e-5f);
        float r3 = rsqrtf(s[7]*inv - mu3*mu3 + 1e-5f);
        float ww = w[tid], wb = bias[tid];
        float an = (a  - mu0)*r0*ww + wb;
        float bn = (bv - mu1)*r1*ww + wb;
        float cn = (cv - mu2)*r2*ww + wb;
        float dn = (dv - mu3)*r3*ww + wb;
        outp[tid]        = __float2bfloat16_rn(( an + bn + cn + dn)*0.5f);
        outp[C_   + tid] = __float2bfloat16_rn((-an - bn + cn + dn)*0.5f);
        outp[2*C_ + tid] = __float2bfloat16_rn((-an + bn - cn + dn)*0.5f);
        outp[3*C_ + tid] = __float2bfloat16_rn(( an - bn - cn + dn)*0.5f);
    }
    if (tid < KP720 - C4) outp[C4 + tid] = __float2bfloat16_rn(0.f);  // pad
}

// ======== bf16 tensor-core GEMM: C = A(M x Kp) @ Wt(Nt x Kp)^T + bias [+epi] ========
// BM=128, BN=96, BK=32, 256 threads (8 warps: 2M x 4N; warp tile 64x24)
// Double-buffered smem: ONE __syncthreads per K-slab.
// A: bf16 row-major, row stride Kp (zero-padded). Wt: bf16 [Nt][Kp] (n-major, k-contig).
// EPI: 0 = bias, 1 = gelu(bias+acc), 2 = bias+acc+Res.  OUT_BF16: write bf16 (+zero pad cols)
#define MMA_BF16(d, a, bfr) \
    asm volatile("mma.sync.aligned.m16n8k16.row.col.f32.bf16.bf16.f32 " \
        "{%0,%1,%2,%3},{%4,%5,%6,%7},{%8,%9},{%0,%1,%2,%3};" \
        : "+f"(d[0]), "+f"(d[1]), "+f"(d[2]), "+f"(d[3]) \
        : "r"(a[0]), "r"(a[1]), "r"(a[2]), "r"(a[3]), "r"(bfr[0]), "r"(bfr[1]))

#define ASZ (128*20)
#define BSZ (96*20)

template<int EPI, bool OUT_BF16>
__global__ void __launch_bounds__(256, 2)
bf16gemm_kernel(const bf16* __restrict__ A, const bf16* __restrict__ Wt,
                const float* __restrict__ bias, const float* __restrict__ Res,
                void* __restrict__ Cout, int M, int N, int Kp, int Cs) {
    __shared__ uint32_t As[2*ASZ];   // [buf][m][k2], stride 20 units (16+4 pad)
    __shared__ uint32_t Bs[2*BSZ];   // [buf][n][k2], stride 20 units

    const int tid  = threadIdx.x;
    const int bm   = blockIdx.y * 128;
    const int bn   = blockIdx.x * 96;
    const int lane = tid & 31;
    const int warp = tid >> 5;
    const int wm   = (warp & 1) * 64;
    const int wn   = (warp >> 1) * 24;
    const int lq   = lane >> 2;
    const int lr   = lane & 3;

    float acc[4][3][4];
    #pragma unroll
    for (int i = 0; i < 4; i++)
        #pragma unroll
        for (int j = 0; j < 3; j++)
            #pragma unroll
            for (int r = 0; r < 4; r++) acc[i][j][r] = 0.f;

    // A: 512 uint4 per tile (128 rows x 4); slots id = tid, tid+256
    const int a_row0 = tid >> 2,        a_q0 = tid & 3;
    const int a_row1 = (tid + 256) >> 2, a_q1 = (tid + 256) & 3;
    // B: 384 uint4 per tile (96 rows x 4); slots id = tid, tid+256 (tid<128)
    const int b_row0 = tid >> 2,        b_q0 = tid & 3;
    const int b_row1 = (tid + 256) >> 2, b_q1 = (tid + 256) & 3;
    const bool b_has1 = (tid < 128);

    const bf16* Abase0 = A + (size_t)(bm + a_row0) * Kp + a_q0 * 8;
    const bf16* Abase1 = A + (size_t)(bm + a_row1) * Kp + a_q1 * 8;
    const bf16* Bbase0 = Wt + (size_t)(bn + b_row0) * Kp + b_q0 * 8;
    const bf16* Bbase1 = Wt + (size_t)(bn + b_row1) * Kp + b_q1 * 8;

    const int niter = Kp >> 5;

    // ---- prologue: load + store slab 0 into buffer 0 ----
    {
        uint4 aP0 = *(const uint4*)(Abase0);
        uint4 aP1 = *(const uint4*)(Abase1);
        uint4 bP0 = *(const uint4*)(Bbase0);
        uint4 bP1 = make_uint4(0u,0u,0u,0u);
        if (b_has1) bP1 = *(const uint4*)(Bbase1);
        *(uint4*)&As[a_row0*20 + a_q0*4] = aP0;
        *(uint4*)&As[a_row1*20 + a_q1*4] = aP1;
        *(uint4*)&Bs[b_row0*20 + b_q0*4] = bP0;
        if (b_has1) *(uint4*)&Bs[b_row1*20 + b_q1*4] = bP1;
    }
    __syncthreads();

    for (int it = 0; it < niter; it++) {
        const int cur = it & 1;
        const uint32_t* Ac = As + cur*ASZ;
        const uint32_t* Bc = Bs + cur*BSZ;
        uint32_t* An = As + (cur^1)*ASZ;
        uint32_t* Bn = Bs + (cur^1)*BSZ;

        // prefetch next slab into registers (issued before compute -> overlap)
        uint4 aP0, aP1, bP0, bP1;
        const bool more = (it + 1 < niter);
        if (more) {
            const int k0 = (it + 1) << 5;
            aP0 = *(const uint4*)(Abase0 + k0);
            aP1 = *(const uint4*)(Abase1 + k0);
            bP0 = *(const uint4*)(Bbase0 + k0);
            if (b_has1) bP1 = *(const uint4*)(Bbase1 + k0);
        }

        // compute current slab: 2 k-steps of 8
        #pragma unroll
        for (int ks = 0; ks < 2; ks++) {
            const int ku = ks * 8;
            uint32_t af[4][4], bfr[3][2];
            #pragma unroll
            for (int mt = 0; mt < 4; mt++) {
                const int base = wm + mt*16 + lq;
                af[mt][0] = Ac[ base    *20 + ku + lr    ];
                af[mt][1] = Ac[(base+8) *20 + ku + lr    ];
                af[mt][2] = Ac[ base    *20 + ku + lr + 4];
                af[mt][3] = Ac[(base+8) *20 + ku + lr + 4];
            }
            #pragma unroll
            for (int nt = 0; nt < 3; nt++) {
                const int nb = wn + nt*8 + lq;
                bfr[nt][0] = Bc[nb*20 + ku + lr    ];
                bfr[nt][1] = Bc[nb*20 + ku + lr + 4];
            }
            #pragma unroll
            for (int mt = 0; mt < 4; mt++)
                #pragma unroll
                for (int nt = 0; nt < 3; nt++)
                    MMA_BF16(acc[mt][nt], af[mt], bfr[nt]);
        }

        // store next slab into the other buffer; one barrier per slab
        if (more) {
            *(uint4*)&An[a_row0*20 + a_q0*4] = aP0;
            *(uint4*)&An[a_row1*20 + a_q1*4] = aP1;
            *(uint4*)&Bn[b_row0*20 + b_q0*4] = bP0;
            if (b_has1) *(uint4*)&Bn[b_row1*20 + b_q1*4] = bP1;
            __syncthreads();
        }
    }

    // ---- epilogue ----
    #pragma unroll
    for (int mt = 0; mt < 4; mt++) {
        const int row0 = bm + wm + mt*16 + lq;
        const int row1 = row0 + 8;
        #pragma unroll
        for (int nt = 0; nt < 3; nt++) {
            const int col = bn + wn + nt*8 + 2*lr;
            if (col < N) {
                const float b0 = bias[col], b1 = bias[col + 1];
                float v0 = acc[mt][nt][0] + b0;
                float v1 = acc[mt][nt][1] + b1;
                float v2 = acc[mt][nt][2] + b0;
                float v3 = acc[mt][nt][3] + b1;
                if (EPI == 1) {
                    v0 = gelu_f(v0); v1 = gelu_f(v1);
                    v2 = gelu_f(v2); v3 = gelu_f(v3);
                }
                if (EPI == 2) {
                    const float* r0p = Res + (size_t)row0*N + col;
                    const float* r1p = Res + (size_t)row1*N + col;
                    v0 += r0p[0]; v1 += r0p[1];
                    v2 += r1p[0]; v3 += r1p[1];
                }
                if (OUT_BF16) {
                    bf16* C = (bf16*)Cout;
                    *(__nv_bfloat162*)(C + (size_t)row0*Cs + col) =
                        __floats2bfloat162_rn(v0, v1);
                    *(__nv_bfloat162*)(C + (size_t)row1*Cs + col) =
                        __floats2bfloat162_rn(v2, v3);
                } else {
                    float* C = (float*)Cout;
                    *(float2*)(C + (size_t)row0*Cs + col) = make_float2(v0, v1);
                    *(float2*)(C + (size_t)row1*Cs + col) = make_float2(v2, v3);
                }
            } else if (OUT_BF16 && col < Cs) {
                bf16* C = (bf16*)Cout;
                __nv_bfloat162 z = __floats2bfloat162_rn(0.f, 0.f);
                *(__nv_bfloat162*)(C + (size_t)row0*Cs + col) = z;
                *(__nv_bfloat162*)(C + (size_t)row1*Cs + col) = z;
            }
        }
    }
}

// -------- windowed attention: one block per (window, head); 2 query rows/pass --------
#define SKROWS 160
#define ATTN_SMEM ((NQ*D_ + SKROWS*31 + NK*60 + 8*2*NK) * 4)

__global__ void attn_kernel(const int* __restrict__ rpi, const float* __restrict__ rpb) {
    extern __shared__ float sm[];
    float*    sQ  = sm;                       // 64*30
    float*    sK  = sQ + NQ*D_;               // 160*31 (rows 144.. zeroed)
    uint32_t* sVh = (uint32_t*)(sK + SKROWS*31); // 144*60 bf162 units
    float*    sP  = (float*)(sVh + NK*60);    // 8 warps * 2 rows * 144

    int blk  = blockIdx.x;
    int head = blk % NH_;
    int win  = blk / NH_;
    int wx = win % 16;
    int wy = (win / 16) % 16;
    int b  = win / 256;
    int tid = threadIdx.x;          // 256

    const float scale = rsqrtf((float)D_);
    for (int i = tid; i < NQ*D_; i += 256) {
        int qr = i / D_, d = i - qr*D_;
        int qy = qr >> 3, qx = qr & 7;
        sQ[i] = g_q[(((size_t)(b*H2 + wy*8+qy))*W2 + wx*8+qx)*C_ + head*D_ + d] * scale;
    }
    for (int i = tid; i < NK*D_; i += 256) {
        int kr = i / D_, d = i - kr*D_;
        int iy = kr / 12, ix = kr - iy*12;
        int y2 = wy*8 + iy - 4, x2 = wx*8 + ix - 4;
        float val = 0.f;
        if ((unsigned)y2 < (unsigned)H2 && (unsigned)x2 < (unsigned)W2)
            val = g_k[(((size_t)(b*H2 + y2))*W2 + x2)*C_ + head*D_ + d];
        sK[kr*31 + d] = val;
    }
    for (int i = tid; i < (SKROWS - NK)*31; i += 256) sK[NK*31 + i] = 0.f;
    // V: 144 rows x 15 uint4 (120 bf16 per row)
    for (int i = tid; i < NK*15; i += 256) {
        int kr = i / 15, u = i - kr*15;
        int iy = kr / 12, ix = kr - iy*12;
        int y2 = wy*8 + iy - 4, x2 = wx*8 + ix - 4;
        uint4 val = make_uint4(0u,0u,0u,0u);
        if ((unsigned)y2 < (unsigned)H2 && (unsigned)x2 < (unsigned)W2) {
            const bf16* src = g_vh + (((size_t)(b*H2 + y2))*W2 + x2)*KP720 + head*DV + u*8;
            val = *(const uint4*)src;
        }
        *(uint4*)&sVh[kr*60 + u*4] = val;
    }
    __syncthreads();

    int warp = tid >> 5, lane = tid & 31;
    float* p0s = sP + warp*2*NK;
    float* p1s = p0s + NK;
    const int qbase = warp * 8;

    for (int pass = 0; pass < 4; pass++) {
        const int r0 = qbase + pass*2, r1 = r0 + 1;
        // scores for 5 key chunks x 2 rows
        float a0[5], a1[5];
        #pragma unroll
        for (int j = 0; j < 5; j++) {
            int kk = lane + j*32;
            if (kk < NK) {
                a0[j] = rpb[rpi[r0*NK + kk]*NH_ + head];
                a1[j] = rpb[rpi[r1*NK + kk]*NH_ + head];
            } else { a0[j] = 0.f; a1[j] = 0.f; }
        }
        const float* q0p = sQ + r0*D_;
        const float* q1p = sQ + r1*D_;
        #pragma unroll
        for (int d = 0; d < D_; d++) {
            float qa = q0p[d], qb = q1p[d];
            #pragma unroll
            for (int j = 0; j < 5; j++) {
                float kv = sK[(lane + j*32)*31 + d];
                a0[j] = fmaf(qa, kv, a0[j]);
                a1[j] = fmaf(qb, kv, a1[j]);
            }
        }
        float mx0 = -1e30f, mx1 = -1e30f;
        #pragma unroll
        for (int j = 0; j < 5; j++) {
            int kk = lane + j*32;
            if (kk >= NK) { a0[j] = -1e30f; a1[j] = -1e30f; }
            mx0 = fmaxf(mx0, a0[j]); mx1 = fmaxf(mx1, a1[j]);
        }
        #pragma unroll
        for (int off = 16; off; off >>= 1) {
            mx0 = fmaxf(mx0, __shfl_xor_sync(0xffffffffu, mx0, off));
            mx1 = fmaxf(mx1, __shfl_xor_sync(0xffffffffu, mx1, off));
        }
        float sum0 = 0.f, sum1 = 0.f;
        #pragma unroll
        for (int j = 0; j < 5; j++) {
            int kk = lane + j*32;
            float e0 = (kk < NK) ? __expf(a0[j] - mx0) : 0.f;
            float e1 = (kk < NK) ? __expf(a1[j] - mx1) : 0.f;
            a0[j] = e0; a1[j] = e1; sum0 += e0; sum1 += e1;
        }
        #pragma unroll
        for (int off = 16; off; off >>= 1) {
            sum0 += __shfl_xor_sync(0xffffffffu, sum0, off);
            sum1 += __shfl_xor_sync(0xffffffffu, sum1, off);
        }
        float inv0 = 1.0f / sum0, inv1 = 1.0f / sum1;
        #pragma unroll
        for (int j = 0; j < 5; j++) {
            int kk = lane + j*32;
            if (kk < NK) { p0s[kk] = a0[j]*inv0; p1s[kk] = a1[j]*inv1; }
        }
        __syncwarp();
        if (lane < 30) {
            float4 o0 = make_float4(0.f,0.f,0.f,0.f);
            float4 o1 = make_float4(0.f,0.f,0.f,0.f);
            #pragma unroll 4
            for (int kk = 0; kk < NK; kk++) {
                float pa = p0s[kk], pb = p1s[kk];
                uint2 vv = *(uint2*)&sVh[kk*60 + lane*2];
                float2 va = __bfloat1622float2(*(__nv_bfloat162*)&vv.x);
                float2 vb = __bfloat1622float2(*(__nv_bfloat162*)&vv.y);
                o0.x = fmaf(pa, va.x, o0.x); o0.y = fmaf(pa, va.y, o0.y);
                o0.z = fmaf(pa, vb.x, o0.z); o0.w = fmaf(pa, vb.y, o0.w);
                o1.x = fmaf(pb, va.x, o1.x); o1.y = fmaf(pb, va.y, o1.y);
                o1.z = fmaf(pb, vb.x, o1.z); o1.w = fmaf(pb, vb.y, o1.w);
            }
            int qy0 = r0 >> 3, qx0 = r0 & 7;
            int qy1 = r1 >> 3, qx1 = r1 & 7;
            *(float4*)(g_o + (((size_t)(b*H2 + wy*8+qy0))*W2 + wx*8+qx0)*C4
                           + head*DV + lane*4) = o0;
            *(float4*)(g_o + (((size_t)(b*H2 + wy*8+qy1))*W2 + wx*8+qx1)*C4
                           + head*DV + lane*4) = o1;
        }
        __syncwarp();
    }
}

// -------- inverse DWT: g_o (b,128,128,720) fp32 -> g_xrh (b,256,256,[192]) bf16 --------
__global__ void idwt_kernel() {
    int idx = blockIdx.x * blockDim.x + threadIdx.x;
    if (idx >= NPOS2 * KP180) return;
    int c   = idx % KP180;
    int pos = idx / KP180;
    int x2 = pos & 127; int t = pos >> 7;
    int y2 = t & 127;   int b = t >> 7;
    bf16* base = g_xrh + (((size_t)(b*HH + 2*y2))*WWF + 2*x2)*KP180 + c;
    if (c < C_) {
        const float* op = g_o + (size_t)pos*C4 + c;
        float ll = op[0], lh = op[C_], hl = op[2*C_], hh = op[3*C_];
        base[0]                   = __float2bfloat16_rn((ll - lh - hl + hh)*0.5f);
        base[KP180]               = __float2bfloat16_rn((ll - lh + hl - hh)*0.5f);
        base[(size_t)WWF*KP180]         = __float2bfloat16_rn((ll + lh - hl - hh)*0.5f);
        base[(size_t)WWF*KP180 + KP180] = __float2bfloat16_rn((ll + lh + hl + hh)*0.5f);
    } else {
        bf16 z = __float2bfloat16_rn(0.f);
        base[0] = z; base[KP180] = z;
        base[(size_t)WWF*KP180] = z; base[(size_t)WWF*KP180 + KP180] = z;
    }
}

// -------- LayerNorm2 (warp per token): g_x1 fp32 -> g_lnh bf16 (padded) --------
__global__ void ln2_kernel(const float* __restrict__ w, const float* __restrict__ bias) {
    int gw   = (blockIdx.x * blockDim.x + threadIdx.x) >> 5;
    int lane = threadIdx.x & 31;
    if (gw >= NTOK) return;
    const float* row = g_x1 + (size_t)gw*C_;
    float v[6]; float s = 0.f, ss = 0.f;
    #pragma unroll
    for (int j = 0; j < 6; j++) {
        int c = lane + j*32;
        float val = (c < C_) ? row[c] : 0.f;
        v[j] = val; s += val; ss = fmaf(val, val, ss);
    }
    #pragma unroll
    for (int off = 16; off; off >>= 1) {
        s  += __shfl_xor_sync(0xffffffffu, s,  off);
        ss += __shfl_xor_sync(0xffffffffu, ss, off);
    }
    float mu  = s * (1.0f/(float)C_);
    float var = ss * (1.0f/(float)C_) - mu*mu;
    float r   = rsqrtf(var + 1e-5f);
    bf16* orow = g_lnh + (size_t)gw*KP180;
    #pragma unroll
    for (int j = 0; j < 6; j++) {
        int c = lane + j*32;
        float ov = (c < C_) ? (v[j] - mu)*r*w[c] + bias[c] : 0.f;
        if (c < KP180) orow[c] = __float2bfloat16_rn(ov);
    }
}

extern "C" void kernel_launch(void* const* d_in, const int* in_sizes, int n_in,
                              void* d_out, int out_size) {
    const float* x   = (const float*)d_in[0];
    const int*   rpi = (const int*)  d_in[2];
    const float* n1w = (const float*)d_in[5];
    const float* n1b = (const float*)d_in[6];
    const float* qw  = (const float*)d_in[9];
    const float* qb  = (const float*)d_in[10];
    const float* kw_ = (const float*)d_in[11];
    const float* kb  = (const float*)d_in[12];
    const float* vw  = (const float*)d_in[13];
    const float* vb  = (const float*)d_in[14];
    const float* rpb = (const float*)d_in[15];
    const float* pw  = (const float*)d_in[16];
    const float* pb  = (const float*)d_in[17];
    const float* n2w = (const float*)d_in[18];
    const float* n2b = (const float*)d_in[19];
    const float* f1w = (const float*)d_in[20];
    const float* f1b = (const float*)d_in[21];
    const float* f2w = (const float*)d_in[22];
    const float* f2b = (const float*)d_in[23];
    float* out = (float*)d_out;

    bf16 *p_xdh, *p_vh, *p_xrh, *p_lnh, *p_hh;
    bf16 *p_wtq, *p_wtk, *p_wtv, *p_wtp, *p_wtf1, *p_wtf2;
    float *p_q, *p_k, *p_x1;
    cudaGetSymbolAddress((void**)&p_xdh, g_xdh);
    cudaGetSymbolAddress((void**)&p_vh,  g_vh);
    cudaGetSymbolAddress((void**)&p_xrh, g_xrh);
    cudaGetSymbolAddress((void**)&p_lnh, g_lnh);
    cudaGetSymbolAddress((void**)&p_hh,  g_hh);
    cudaGetSymbolAddress((void**)&p_wtq, g_wtq);
    cudaGetSymbolAddress((void**)&p_wtk, g_wtk);
    cudaGetSymbolAddress((void**)&p_wtv, g_wtv);
    cudaGetSymbolAddress((void**)&p_wtp, g_wtp);
    cudaGetSymbolAddress((void**)&p_wtf1, g_wtf1);
    cudaGetSymbolAddress((void**)&p_wtf2, g_wtf2);
    cudaGetSymbolAddress((void**)&p_q,  g_q);
    cudaGetSymbolAddress((void**)&p_k,  g_k);
    cudaGetSymbolAddress((void**)&p_x1, g_x1);

    // weight prep (transpose + bf16 + pad)
    {
        int n;
        n = 192*KP720; wprep_kernel<<<(n+255)/256,256>>>(qw,  p_wtq,  C4, C_,  KP720, 192);
        n = 192*KP720; wprep_kernel<<<(n+255)/256,256>>>(kw_, p_wtk,  C4, C_,  KP720, 192);
        n = 768*KP720; wprep_kernel<<<(n+255)/256,256>>>(vw,  p_wtv,  C4, C4,  KP720, 768);
        n = 192*KP180; wprep_kernel<<<(n+255)/256,256>>>(pw,  p_wtp,  C_, C_,  KP180, 192);
        n = 384*KP180; wprep_kernel<<<(n+255)/256,256>>>(f1w, p_wtf1, C_, 2*C_, KP180, 384);
        n = 192*KP360; wprep_kernel<<<(n+255)/256,256>>>(f2w, p_wtf2, 2*C_, C_, KP360, 192);
    }

    // 1) LN(norm1) + DWT -> g_xdh (bf16)
    ln_dwt_kernel<<<NPOS2, 192>>>(x, n1w, n1b);

    // 2,3) q,k projections (M=32768, N=180, Kp=736) -> fp32
    {
        dim3 g(2, NPOS2/128);
        bf16gemm_kernel<0,false><<<g, 256>>>(p_xdh, p_wtq, qb, nullptr, p_q, NPOS2, C_, KP720, C_);
        bf16gemm_kernel<0,false><<<g, 256>>>(p_xdh, p_wtk, kb, nullptr, p_k, NPOS2, C_, KP720, C_);
    }
    // 4) v projection (N=720) -> bf16 padded
    {
        dim3 g(8, NPOS2/128);
        bf16gemm_kernel<0,true><<<g, 256>>>(p_xdh, p_wtv, vb, nullptr, p_vh, NPOS2, C4, KP720, KP720);
    }
    // 5) windowed attention -> g_o (fp32)
    cudaFuncSetAttribute(attn_kernel, cudaFuncAttributeMaxDynamicSharedMemorySize, ATTN_SMEM);
    attn_kernel<<<NWIN*NH_, 256, ATTN_SMEM>>>(rpi, rpb);

    // 6) inverse DWT -> g_xrh (bf16 padded)
    idwt_kernel<<<(NPOS2*KP180 + 255)/256, 256>>>();

    // 7) proj + residual -> g_x1 (fp32)   (M=131072, N=180, Kp=192)
    {
        dim3 g(2, NTOK/128);
        bf16gemm_kernel<2,false><<<g, 256>>>(p_xrh, p_wtp, pb, x, p_x1, NTOK, C_, KP180, C_);
    }
    // 8) LN(norm2) -> g_lnh (bf16 padded)
    ln2_kernel<<<NTOK/8, 256>>>(n2w, n2b);

    // 9) fc1 + gelu -> g_hh (bf16 padded)  (N=360, Kp=192)
    {
        dim3 g(4, NTOK/128);
        bf16gemm_kernel<1,true><<<g, 256>>>(p_lnh, p_wtf1, f1b, nullptr, p_hh, NTOK, 2*C_, KP180, KP360);
    }
    // 10) fc2 + residual(g_x1) -> out (fp32)  (N=180, Kp=384)
    {
        dim3 g(2, NTOK/128);
        bf16gemm_kernel<2,false><<<g, 256>>>(p_hh, p_wtf2, f2b, p_x1, out, NTOK, C_, KP360, C_);
    }
}